// round 1
// baseline (speedup 1.0000x reference)
#include <cuda_runtime.h>
#include <math.h>

#define B_   4
#define N_   1024
#define D_   1024
#define H_   16
#define HD_  64
#define FF_  4096
#define M_   (B_ * N_)   // 4096 rows

// ---------------- scratch (static device globals; no allocs allowed) ----------------
__device__ float g_q [M_ * D_];
__device__ float g_k [M_ * D_];
__device__ float g_v [M_ * D_];
__device__ float g_ao[M_ * D_];
__device__ float g_t [M_ * D_];   // src2 / ffn2 output temp
__device__ float g_x [M_ * D_];   // post-LN1 activations
__device__ float g_ff[M_ * FF_];  // ffn hidden

// ---------------- SGEMM: C[M,Nn] = A[M,K] @ W[Nn,K]^T (+bias) (+gelu) ----------------
// 128x128 block tile, BK=8, 256 threads, 8x8 per-thread microtile.
template <int ACT>
__global__ __launch_bounds__(256)
void sgemm_kernel(const float* __restrict__ A, const float* __restrict__ W,
                  const float* __restrict__ bias, float* __restrict__ C,
                  int M, int Nn, int K) {
    __shared__ float As[8][128];
    __shared__ float Ws[8][128];

    const int tid   = threadIdx.x;
    const int mBase = blockIdx.y * 128;
    const int nBase = blockIdx.x * 128;
    const int lr = tid >> 1;          // 0..127 row within tile
    const int lc = (tid & 1) * 4;     // 0 or 4
    const int tx = tid & 15;
    const int ty = tid >> 4;

    float acc[8][8];
#pragma unroll
    for (int i = 0; i < 8; i++)
#pragma unroll
        for (int j = 0; j < 8; j++) acc[i][j] = 0.f;

    const float* Ap = A + (size_t)(mBase + lr) * K + lc;
    const float* Wp = W + (size_t)(nBase + lr) * K + lc;

    for (int k0 = 0; k0 < K; k0 += 8) {
        float4 a4 = *(const float4*)(Ap + k0);
        float4 w4 = *(const float4*)(Wp + k0);
        As[lc + 0][lr] = a4.x; As[lc + 1][lr] = a4.y;
        As[lc + 2][lr] = a4.z; As[lc + 3][lr] = a4.w;
        Ws[lc + 0][lr] = w4.x; Ws[lc + 1][lr] = w4.y;
        Ws[lc + 2][lr] = w4.z; Ws[lc + 3][lr] = w4.w;
        __syncthreads();

#pragma unroll
        for (int kk = 0; kk < 8; kk++) {
            float am[8], wn[8];
#pragma unroll
            for (int i = 0; i < 8; i++) am[i] = As[kk][ty * 8 + i];
#pragma unroll
            for (int j = 0; j < 8; j++) wn[j] = Ws[kk][tx * 8 + j];
#pragma unroll
            for (int i = 0; i < 8; i++)
#pragma unroll
                for (int j = 0; j < 8; j++)
                    acc[i][j] = fmaf(am[i], wn[j], acc[i][j]);
        }
        __syncthreads();
    }

#pragma unroll
    for (int i = 0; i < 8; i++) {
        const int r = mBase + ty * 8 + i;
#pragma unroll
        for (int j = 0; j < 8; j++) {
            const int c = nBase + tx * 8 + j;
            float v = acc[i][j];
            if (bias) v += bias[c];
            if (ACT == 1) v = 0.5f * v * (1.f + erff(v * 0.70710678118654752f));
            C[(size_t)r * Nn + c] = v;
        }
    }
}

// ---------------- attention: per-thread query row, online softmax ----------------
// grid = B*H*(N/128) = 512 blocks, 128 threads. Thread owns one query row.
// bias = slope[h] * (|dx|+|dy|)  (R_LEFT == R_RIGHT == 1 collapses the le() term).
__global__ __launch_bounds__(128)
void attn_kernel(const float* __restrict__ q, const float* __restrict__ k,
                 const float* __restrict__ v, const int* __restrict__ coords,
                 float* __restrict__ out) {
    const int gid  = blockIdx.x;
    const int tile = gid & 7;
    const int h    = (gid >> 3) & 15;
    const int b    = gid >> 7;
    const int n    = tile * 128 + threadIdx.x;
    const int row  = b * N_ + n;

    const float slope = exp2f(-0.5f * (float)(h + 1));
    const float scale = 0.125f;  // 64^-0.5

    __shared__ float Ks[16][64];
    __shared__ float Vs[16][64];
    __shared__ float xs[16], ys[16];

    float qr[64];
    const float* qp = q + (size_t)row * D_ + h * HD_;
#pragma unroll
    for (int i = 0; i < 16; i++) {
        float4 t = *(const float4*)(qp + 4 * i);
        qr[4*i] = t.x; qr[4*i+1] = t.y; qr[4*i+2] = t.z; qr[4*i+3] = t.w;
    }
    const float xi = (float)coords[row * 2 + 0];
    const float yi = (float)coords[row * 2 + 1];

    float m = -1e30f, l = 0.f;
    float acc[64];
#pragma unroll
    for (int d = 0; d < 64; d++) acc[d] = 0.f;

    for (int kt = 0; kt < N_; kt += 16) {
        // cooperative tile load: 16 keys x 64 dims for K and V
#pragma unroll
        for (int i = 0; i < 8; i++) {
            const int e = threadIdx.x + 128 * i;
            const int j = e >> 6, d = e & 63;
            const size_t src = (size_t)(b * N_ + kt + j) * D_ + h * HD_ + d;
            Ks[j][d] = k[src];
            Vs[j][d] = v[src];
        }
        if (threadIdx.x < 16) {
            const int krow = b * N_ + kt + threadIdx.x;
            xs[threadIdx.x] = (float)coords[krow * 2 + 0];
            ys[threadIdx.x] = (float)coords[krow * 2 + 1];
        }
        __syncthreads();

        float s[16];
        float tm = -1e30f;
#pragma unroll
        for (int j = 0; j < 16; j++) {
            float dot = 0.f;
#pragma unroll
            for (int d4 = 0; d4 < 16; d4++) {
                float4 kk = *(const float4*)&Ks[j][4 * d4];
                dot = fmaf(qr[4*d4+0], kk.x, dot);
                dot = fmaf(qr[4*d4+1], kk.y, dot);
                dot = fmaf(qr[4*d4+2], kk.z, dot);
                dot = fmaf(qr[4*d4+3], kk.w, dot);
            }
            const float dist = fabsf(xi - xs[j]) + fabsf(yi - ys[j]);
            s[j] = fmaf(dot, scale, slope * dist);
            tm = fmaxf(tm, s[j]);
        }

        const float nm   = fmaxf(m, tm);
        const float corr = __expf(m - nm);
        l *= corr;
#pragma unroll
        for (int d = 0; d < 64; d++) acc[d] *= corr;

#pragma unroll
        for (int j = 0; j < 16; j++) {
            const float p = __expf(s[j] - nm);
            l += p;
#pragma unroll
            for (int d4 = 0; d4 < 16; d4++) {
                float4 vv = *(const float4*)&Vs[j][4 * d4];
                acc[4*d4+0] = fmaf(p, vv.x, acc[4*d4+0]);
                acc[4*d4+1] = fmaf(p, vv.y, acc[4*d4+1]);
                acc[4*d4+2] = fmaf(p, vv.z, acc[4*d4+2]);
                acc[4*d4+3] = fmaf(p, vv.w, acc[4*d4+3]);
            }
        }
        m = nm;
        __syncthreads();
    }

    const float inv = 1.f / l;
    float* op = out + (size_t)row * D_ + h * HD_;
#pragma unroll
    for (int i = 0; i < 16; i++) {
        float4 t;
        t.x = acc[4*i+0] * inv; t.y = acc[4*i+1] * inv;
        t.z = acc[4*i+2] * inv; t.w = acc[4*i+3] * inv;
        *(float4*)(op + 4 * i) = t;
    }
}

// ---------------- fused residual add + LayerNorm (row = 1024 elems) ----------------
__global__ __launch_bounds__(256)
void add_ln_kernel(const float* __restrict__ a, const float* __restrict__ bsum,
                   const float* __restrict__ g, const float* __restrict__ be,
                   float* __restrict__ out) {
    const int row = blockIdx.x;
    const int tid = threadIdx.x;
    const float* pa = a    + (size_t)row * D_;
    const float* pb = bsum + (size_t)row * D_;

    float v[4];
    float s = 0.f, ss = 0.f;
#pragma unroll
    for (int i = 0; i < 4; i++) {
        const int c = tid + 256 * i;
        const float t = pa[c] + pb[c];
        v[i] = t; s += t; ss = fmaf(t, t, ss);
    }
#pragma unroll
    for (int o = 16; o > 0; o >>= 1) {
        s  += __shfl_xor_sync(0xffffffffu, s,  o);
        ss += __shfl_xor_sync(0xffffffffu, ss, o);
    }
    __shared__ float rs[8], rss[8];
    __shared__ float smu, sinv;
    const int w = tid >> 5;
    if ((tid & 31) == 0) { rs[w] = s; rss[w] = ss; }
    __syncthreads();
    if (tid == 0) {
        float S = 0.f, SS = 0.f;
#pragma unroll
        for (int i = 0; i < 8; i++) { S += rs[i]; SS += rss[i]; }
        const float mu  = S * (1.f / 1024.f);
        const float var = SS * (1.f / 1024.f) - mu * mu;
        smu = mu; sinv = rsqrtf(var + 1e-5f);
    }
    __syncthreads();
    const float mu = smu, inv = sinv;
#pragma unroll
    for (int i = 0; i < 4; i++) {
        const int c = tid + 256 * i;
        out[(size_t)row * D_ + c] = (v[i] - mu) * inv * g[c] + be[c];
    }
}

// ---------------- launch ----------------
extern "C" void kernel_launch(void* const* d_in, const int* in_sizes, int n_in,
                              void* d_out, int out_size) {
    const float* src    = (const float*)d_in[0];
    const int*   coords = (const int*)  d_in[1];
    const float* Wq = (const float*)d_in[2];
    const float* Wk = (const float*)d_in[3];
    const float* Wv = (const float*)d_in[4];
    const float* Wo = (const float*)d_in[5];
    const float* W1 = (const float*)d_in[6];
    const float* b1 = (const float*)d_in[7];
    const float* W2 = (const float*)d_in[8];
    const float* b2 = (const float*)d_in[9];
    const float* g1 = (const float*)d_in[10];
    const float* be1= (const float*)d_in[11];
    const float* g2 = (const float*)d_in[12];
    const float* be2= (const float*)d_in[13];
    float* out = (float*)d_out;

    void *pq, *pk, *pv, *pao, *pt, *px, *pff;
    cudaGetSymbolAddress(&pq,  g_q);
    cudaGetSymbolAddress(&pk,  g_k);
    cudaGetSymbolAddress(&pv,  g_v);
    cudaGetSymbolAddress(&pao, g_ao);
    cudaGetSymbolAddress(&pt,  g_t);
    cudaGetSymbolAddress(&px,  g_x);
    cudaGetSymbolAddress(&pff, g_ff);

    const dim3 blk(256);
    const dim3 gD(D_ / 128, M_ / 128);    // (8, 32)
    const dim3 gF(FF_ / 128, M_ / 128);   // (32, 32)

    // QKV projections
    sgemm_kernel<0><<<gD, blk>>>(src, Wq, nullptr, (float*)pq, M_, D_, D_);
    sgemm_kernel<0><<<gD, blk>>>(src, Wk, nullptr, (float*)pk, M_, D_, D_);
    sgemm_kernel<0><<<gD, blk>>>(src, Wv, nullptr, (float*)pv, M_, D_, D_);

    // attention with 2D-ALiBi bias + online softmax
    attn_kernel<<<512, 128>>>((const float*)pq, (const float*)pk, (const float*)pv,
                              coords, (float*)pao);

    // output projection, residual + LN1
    sgemm_kernel<0><<<gD, blk>>>((const float*)pao, Wo, nullptr, (float*)pt, M_, D_, D_);
    add_ln_kernel<<<M_, 256>>>(src, (const float*)pt, g1, be1, (float*)px);

    // FFN (gelu exact), residual + LN2
    sgemm_kernel<1><<<gF, blk>>>((const float*)px, W1, b1, (float*)pff, M_, FF_, D_);
    sgemm_kernel<0><<<gD, blk>>>((const float*)pff, W2, b2, (float*)pt, M_, D_, FF_);
    add_ln_kernel<<<M_, 256>>>((const float*)px, (const float*)pt, g2, be2, out);
}

// round 3
// speedup vs baseline: 2.0460x; 2.0460x over previous
#include <cuda_runtime.h>
#include <cuda_bf16.h>
#include <math.h>
#include <stdint.h>

#define B_   4
#define N_   1024
#define D_   1024
#define H_   16
#define HD_  64
#define FF_  4096
#define M_   (B_ * N_)   // 4096 rows

// ---------------- scratch (static device globals; no allocs allowed) ----------------
__device__ float g_q [M_ * D_];
__device__ float g_k [M_ * D_];
__device__ float g_v [M_ * D_];
__device__ float g_t [M_ * D_];   // src2 / ffn2 output temp (fp32)
__device__ float g_x [M_ * D_];   // post-LN1 activations (fp32)

// bf16 hi/lo split buffers
__device__ __nv_bfloat16 s_src_h[M_ * D_],  s_src_l[M_ * D_];
__device__ __nv_bfloat16 s_wq_h [D_ * D_],  s_wq_l [D_ * D_];
__device__ __nv_bfloat16 s_wk_h [D_ * D_],  s_wk_l [D_ * D_];
__device__ __nv_bfloat16 s_wv_h [D_ * D_],  s_wv_l [D_ * D_];
__device__ __nv_bfloat16 s_wo_h [D_ * D_],  s_wo_l [D_ * D_];
__device__ __nv_bfloat16 s_w1_h [FF_ * D_], s_w1_l [FF_ * D_];
__device__ __nv_bfloat16 s_w2_h [D_ * FF_], s_w2_l [D_ * FF_];
__device__ __nv_bfloat16 s_x_h  [M_ * D_],  s_x_l  [M_ * D_];
__device__ __nv_bfloat16 s_ao_h [M_ * D_],  s_ao_l [M_ * D_];
__device__ __nv_bfloat16 s_ff_h [M_ * FF_], s_ff_l [M_ * FF_];

// ---------------- PTX helpers (Ampere-era only: valid at compute_103 base) ----------
__device__ __forceinline__ uint32_t s2u(const void* p) {
    uint32_t a;
    asm("{ .reg .u64 t; cvta.to.shared.u64 t, %1; cvt.u32.u64 %0, t; }" : "=r"(a) : "l"(p));
    return a;
}
__device__ __forceinline__ void cp_async16(uint32_t saddr, const void* g) {
    asm volatile("cp.async.cg.shared.global [%0], [%1], 16;" :: "r"(saddr), "l"(g) : "memory");
}
#define CP_COMMIT()  asm volatile("cp.async.commit_group;" ::: "memory")
#define CP_WAIT(n)   asm volatile("cp.async.wait_group %0;" :: "n"(n) : "memory")

__device__ __forceinline__ void ldsm4(uint32_t* r, uint32_t addr) {
    asm volatile("ldmatrix.sync.aligned.m8n8.x4.shared.b16 {%0,%1,%2,%3}, [%4];"
                 : "=r"(r[0]), "=r"(r[1]), "=r"(r[2]), "=r"(r[3]) : "r"(addr));
}
__device__ __forceinline__ void mma16816(float* c, const uint32_t* a, const uint32_t* b) {
    asm volatile(
        "mma.sync.aligned.m16n8k16.row.col.f32.bf16.bf16.f32 "
        "{%0,%1,%2,%3}, {%4,%5,%6,%7}, {%8,%9}, {%0,%1,%2,%3};"
        : "+f"(c[0]), "+f"(c[1]), "+f"(c[2]), "+f"(c[3])
        : "r"(a[0]), "r"(a[1]), "r"(a[2]), "r"(a[3]), "r"(b[0]), "r"(b[1]));
}

#define SWZ(o) ((o) ^ (((o) >> 3) & 0x70))

// ---------------- split fp32 -> bf16 (hi, lo) ----------------
__global__ __launch_bounds__(256)
void split_kernel(const float4* __restrict__ x, uint2* __restrict__ hi,
                  uint2* __restrict__ lo, int n4) {
    int i = blockIdx.x * 256 + threadIdx.x;
    if (i >= n4) return;
    float4 v = x[i];
    __nv_bfloat16 hx = __float2bfloat16(v.x), hy = __float2bfloat16(v.y);
    __nv_bfloat16 hz = __float2bfloat16(v.z), hw = __float2bfloat16(v.w);
    __nv_bfloat162 a = __halves2bfloat162(hx, hy);
    __nv_bfloat162 b = __halves2bfloat162(hz, hw);
    hi[i] = make_uint2(*(const uint32_t*)&a, *(const uint32_t*)&b);
    __nv_bfloat162 la = __halves2bfloat162(__float2bfloat16(v.x - __bfloat162float(hx)),
                                           __float2bfloat16(v.y - __bfloat162float(hy)));
    __nv_bfloat162 lb = __halves2bfloat162(__float2bfloat16(v.z - __bfloat162float(hz)),
                                           __float2bfloat16(v.w - __bfloat162float(hw)));
    lo[i] = make_uint2(*(const uint32_t*)&la, *(const uint32_t*)&lb);
}

// ---------------- HMMA GEMM: C[M,Nn] = A[M,K] @ W[Nn,K]^T (3-term bf16 split) -------
// CTA: 128x128 tile, 256 threads (8 warps, 2x4 warp grid, 64x32 per warp).
// BK=64 bf16 (128-byte rows, SW128 swizzle), 2-stage cp.async pipeline.
// smem stage layout: [Ah 16K][Al 16K][Wh 16K][Wl 16K] -> 64KB/stage, 128KB total.
#define STAGE_BYTES 65536
#define GEMM_SMEM_BYTES (2 * STAGE_BYTES)

template <int ACT, int OUTBF16>
__global__ __launch_bounds__(256, 1)
void mma_gemm(const __nv_bfloat16* __restrict__ Ah, const __nv_bfloat16* __restrict__ Al,
              const __nv_bfloat16* __restrict__ Wh, const __nv_bfloat16* __restrict__ Wl,
              const float* __restrict__ bias,
              float* __restrict__ Cf,
              __nv_bfloat16* __restrict__ Ch, __nv_bfloat16* __restrict__ Cl,
              int Nn, int K) {
    extern __shared__ char dsm[];
    const uint32_t sb = s2u(dsm);

    const int tid  = threadIdx.x;
    const int wid  = tid >> 5;
    const int lane = tid & 31;
    const int wm   = wid & 1;        // 0..1  (m direction, 64 rows each)
    const int wn   = wid >> 1;       // 0..3  (n direction, 32 cols each)
    const int mBase = blockIdx.y * 128;
    const int nBase = blockIdx.x * 128;
    const int NC = K / 64;

    const __nv_bfloat16* gsrc[4] = {
        Ah + (size_t)mBase * K, Al + (size_t)mBase * K,
        Wh + (size_t)nBase * K, Wl + (size_t)nBase * K };

    // per-thread cp.async address precompute: 4 chunks per sub-matrix
    const int r0 = tid >> 3;          // 0..31  (row step 32)
    const int c0 = tid & 7;           // 16B chunk within 128B row

    auto load_stage = [&](int buf, int kcol) {
        const uint32_t stage = sb + buf * STAGE_BYTES;
#pragma unroll
        for (int sub = 0; sub < 4; sub++) {
            const __nv_bfloat16* G = gsrc[sub] + kcol;
            const uint32_t soff = stage + sub * 16384;
#pragma unroll
            for (int j = 0; j < 4; j++) {
                const int r = r0 + 32 * j;
                const uint32_t off = (uint32_t)(r * 128 + c0 * 16);
                cp_async16(soff + SWZ(off), G + (size_t)r * K + c0 * 8);
            }
        }
    };

    float acc[4][4][4];
#pragma unroll
    for (int i = 0; i < 4; i++)
#pragma unroll
        for (int j = 0; j < 4; j++)
#pragma unroll
            for (int t = 0; t < 4; t++) acc[i][j][t] = 0.f;

    // ldmatrix base offsets (within a stage's sub-matrix)
    const int aRow = wm * 64 + (lane & 15);
    const int aColSel = (lane >> 4) * 8;
    const int bRow = wn * 32 + ((lane >> 4) << 3) + (lane & 7);
    const int bColSel = ((lane >> 3) & 1) * 8;

    load_stage(0, 0);
    CP_COMMIT();

    for (int c = 0; c < NC; c++) {
        if (c + 1 < NC) {
            load_stage((c + 1) & 1, (c + 1) * 64);
            CP_COMMIT();
            CP_WAIT(1);
        } else {
            CP_WAIT(0);
        }
        __syncthreads();

        const uint32_t stage = sb + (c & 1) * STAGE_BYTES;
        const uint32_t sAh = stage, sAl = stage + 16384;
        const uint32_t sWh = stage + 32768, sWl = stage + 49152;

#pragma unroll
        for (int ks = 0; ks < 4; ks++) {
            const int kc = ks * 16;
            uint32_t ah[4][4], al[4][4];
#pragma unroll
            for (int fm = 0; fm < 4; fm++) {
                const uint32_t off = (uint32_t)((aRow + fm * 16) * 128 + (kc + aColSel) * 2);
                ldsm4(ah[fm], sAh + SWZ(off));
                ldsm4(al[fm], sAl + SWZ(off));
            }
            uint32_t bh[4][2], bl[4][2];
#pragma unroll
            for (int nh = 0; nh < 2; nh++) {
                const uint32_t off = (uint32_t)((bRow + nh * 16) * 128 + (kc + bColSel) * 2);
                uint32_t t[4];
                ldsm4(t, sWh + SWZ(off));
                bh[nh*2][0] = t[0]; bh[nh*2][1] = t[1];
                bh[nh*2+1][0] = t[2]; bh[nh*2+1][1] = t[3];
                ldsm4(t, sWl + SWZ(off));
                bl[nh*2][0] = t[0]; bl[nh*2][1] = t[1];
                bl[nh*2+1][0] = t[2]; bl[nh*2+1][1] = t[3];
            }
#pragma unroll
            for (int fm = 0; fm < 4; fm++)
#pragma unroll
                for (int fn = 0; fn < 4; fn++) {
                    mma16816(acc[fm][fn], ah[fm], bh[fn]);
                    mma16816(acc[fm][fn], ah[fm], bl[fn]);
                    mma16816(acc[fm][fn], al[fm], bh[fn]);
                }
        }
        __syncthreads();
    }

    // ---- epilogue: regs -> gmem with bias / gelu / bf16 hi-lo split ----
    const int erow = mBase + wm * 64 + (lane >> 2);
    const int ecol = nBase + wn * 32 + (lane & 3) * 2;
#pragma unroll
    for (int fm = 0; fm < 4; fm++) {
#pragma unroll
        for (int fn = 0; fn < 4; fn++) {
            const int col = ecol + fn * 8;
#pragma unroll
            for (int half = 0; half < 2; half++) {
                const int row = erow + fm * 16 + half * 8;
                float v0 = acc[fm][fn][half * 2 + 0];
                float v1 = acc[fm][fn][half * 2 + 1];
                if (bias) { v0 += bias[col]; v1 += bias[col + 1]; }
                if (ACT == 1) {
                    v0 = 0.5f * v0 * (1.f + erff(v0 * 0.70710678118654752f));
                    v1 = 0.5f * v1 * (1.f + erff(v1 * 0.70710678118654752f));
                }
                const size_t base = (size_t)row * Nn + col;
                if (OUTBF16) {
                    __nv_bfloat16 h0 = __float2bfloat16(v0);
                    __nv_bfloat16 h1 = __float2bfloat16(v1);
                    __nv_bfloat162 hp = __halves2bfloat162(h0, h1);
                    *(uint32_t*)(Ch + base) = *(const uint32_t*)&hp;
                    __nv_bfloat162 lp = __halves2bfloat162(
                        __float2bfloat16(v0 - __bfloat162float(h0)),
                        __float2bfloat16(v1 - __bfloat162float(h1)));
                    *(uint32_t*)(Cl + base) = *(const uint32_t*)&lp;
                } else {
                    *(float2*)(Cf + base) = make_float2(v0, v1);
                }
            }
        }
    }
}

// ---------------- attention: per-thread query row, online softmax ----------------
__global__ __launch_bounds__(128)
void attn_kernel(const float* __restrict__ q, const float* __restrict__ k,
                 const float* __restrict__ v, const int* __restrict__ coords,
                 __nv_bfloat16* __restrict__ ao_h, __nv_bfloat16* __restrict__ ao_l) {
    const int gid  = blockIdx.x;
    const int tile = gid & 7;
    const int h    = (gid >> 3) & 15;
    const int b    = gid >> 7;
    const int n    = tile * 128 + threadIdx.x;
    const int row  = b * N_ + n;

    const float slope = exp2f(-0.5f * (float)(h + 1));
    const float scale = 0.125f;

    __shared__ float Ks[16][64];
    __shared__ float Vs[16][64];
    __shared__ float xs[16], ys[16];

    float qr[64];
    const float* qp = q + (size_t)row * D_ + h * HD_;
#pragma unroll
    for (int i = 0; i < 16; i++) {
        float4 t = *(const float4*)(qp + 4 * i);
        qr[4*i] = t.x; qr[4*i+1] = t.y; qr[4*i+2] = t.z; qr[4*i+3] = t.w;
    }
    const float xi = (float)coords[row * 2 + 0];
    const float yi = (float)coords[row * 2 + 1];

    float m = -1e30f, l = 0.f;
    float acc[64];
#pragma unroll
    for (int d = 0; d < 64; d++) acc[d] = 0.f;

    for (int kt = 0; kt < N_; kt += 16) {
#pragma unroll
        for (int i = 0; i < 8; i++) {
            const int e = threadIdx.x + 128 * i;
            const int j = e >> 6, d = e & 63;
            const size_t src = (size_t)(b * N_ + kt + j) * D_ + h * HD_ + d;
            Ks[j][d] = k[src];
            Vs[j][d] = v[src];
        }
        if (threadIdx.x < 16) {
            const int krow = b * N_ + kt + threadIdx.x;
            xs[threadIdx.x] = (float)coords[krow * 2 + 0];
            ys[threadIdx.x] = (float)coords[krow * 2 + 1];
        }
        __syncthreads();

        float s[16];
        float tm = -1e30f;
#pragma unroll
        for (int j = 0; j < 16; j++) {
            float dot = 0.f;
#pragma unroll
            for (int d4 = 0; d4 < 16; d4++) {
                float4 kk = *(const float4*)&Ks[j][4 * d4];
                dot = fmaf(qr[4*d4+0], kk.x, dot);
                dot = fmaf(qr[4*d4+1], kk.y, dot);
                dot = fmaf(qr[4*d4+2], kk.z, dot);
                dot = fmaf(qr[4*d4+3], kk.w, dot);
            }
            const float dist = fabsf(xi - xs[j]) + fabsf(yi - ys[j]);
            s[j] = fmaf(dot, scale, slope * dist);
            tm = fmaxf(tm, s[j]);
        }

        const float nm   = fmaxf(m, tm);
        const float corr = __expf(m - nm);
        l *= corr;
#pragma unroll
        for (int d = 0; d < 64; d++) acc[d] *= corr;

#pragma unroll
        for (int j = 0; j < 16; j++) {
            const float p = __expf(s[j] - nm);
            l += p;
#pragma unroll
            for (int d4 = 0; d4 < 16; d4++) {
                float4 vv = *(const float4*)&Vs[j][4 * d4];
                acc[4*d4+0] = fmaf(p, vv.x, acc[4*d4+0]);
                acc[4*d4+1] = fmaf(p, vv.y, acc[4*d4+1]);
                acc[4*d4+2] = fmaf(p, vv.z, acc[4*d4+2]);
                acc[4*d4+3] = fmaf(p, vv.w, acc[4*d4+3]);
            }
        }
        m = nm;
        __syncthreads();
    }

    const float inv = 1.f / l;
    __nv_bfloat16* oh = ao_h + (size_t)row * D_ + h * HD_;
    __nv_bfloat16* ol = ao_l + (size_t)row * D_ + h * HD_;
#pragma unroll
    for (int i = 0; i < 32; i++) {
        const float v0 = acc[2*i]   * inv;
        const float v1 = acc[2*i+1] * inv;
        const __nv_bfloat16 h0 = __float2bfloat16(v0);
        const __nv_bfloat16 h1 = __float2bfloat16(v1);
        __nv_bfloat162 hp = __halves2bfloat162(h0, h1);
        *(uint32_t*)(oh + 2*i) = *(const uint32_t*)&hp;
        __nv_bfloat162 lp = __halves2bfloat162(
            __float2bfloat16(v0 - __bfloat162float(h0)),
            __float2bfloat16(v1 - __bfloat162float(h1)));
        *(uint32_t*)(ol + 2*i) = *(const uint32_t*)&lp;
    }
}

// ---------------- fused residual add + LayerNorm (+ optional bf16 hi/lo emit) -------
__global__ __launch_bounds__(256)
void add_ln_kernel(const float* __restrict__ a, const float* __restrict__ bsum,
                   const float* __restrict__ g, const float* __restrict__ be,
                   float* __restrict__ out,
                   __nv_bfloat16* __restrict__ hi, __nv_bfloat16* __restrict__ lo) {
    const int row = blockIdx.x;
    const int tid = threadIdx.x;
    const float* pa = a    + (size_t)row * D_;
    const float* pb = bsum + (size_t)row * D_;

    float v[4];
    float s = 0.f, ss = 0.f;
#pragma unroll
    for (int i = 0; i < 4; i++) {
        const int c = tid + 256 * i;
        const float t = pa[c] + pb[c];
        v[i] = t; s += t; ss = fmaf(t, t, ss);
    }
#pragma unroll
    for (int o = 16; o > 0; o >>= 1) {
        s  += __shfl_xor_sync(0xffffffffu, s,  o);
        ss += __shfl_xor_sync(0xffffffffu, ss, o);
    }
    __shared__ float rs[8], rss[8];
    __shared__ float smu, sinv;
    const int w = tid >> 5;
    if ((tid & 31) == 0) { rs[w] = s; rss[w] = ss; }
    __syncthreads();
    if (tid == 0) {
        float S = 0.f, SS = 0.f;
#pragma unroll
        for (int i = 0; i < 8; i++) { S += rs[i]; SS += rss[i]; }
        const float mu  = S * (1.f / 1024.f);
        const float var = SS * (1.f / 1024.f) - mu * mu;
        smu = mu; sinv = rsqrtf(var + 1e-5f);
    }
    __syncthreads();
    const float mu = smu, inv = sinv;
#pragma unroll
    for (int i = 0; i < 4; i++) {
        const int c = tid + 256 * i;
        const float o = (v[i] - mu) * inv * g[c] + be[c];
        out[(size_t)row * D_ + c] = o;
        if (hi) {
            const __nv_bfloat16 hh = __float2bfloat16(o);
            hi[(size_t)row * D_ + c] = hh;
            lo[(size_t)row * D_ + c] = __float2bfloat16(o - __bfloat162float(hh));
        }
    }
}

// ---------------- launch ----------------
extern "C" void kernel_launch(void* const* d_in, const int* in_sizes, int n_in,
                              void* d_out, int out_size) {
    const float* src    = (const float*)d_in[0];
    const int*   coords = (const int*)  d_in[1];
    const float* Wq = (const float*)d_in[2];
    const float* Wk = (const float*)d_in[3];
    const float* Wv = (const float*)d_in[4];
    const float* Wo = (const float*)d_in[5];
    const float* W1 = (const float*)d_in[6];
    const float* b1 = (const float*)d_in[7];
    const float* W2 = (const float*)d_in[8];
    const float* b2 = (const float*)d_in[9];
    const float* g1 = (const float*)d_in[10];
    const float* be1= (const float*)d_in[11];
    const float* g2 = (const float*)d_in[12];
    const float* be2= (const float*)d_in[13];
    float* out = (float*)d_out;

    void *pq, *pk, *pv, *pt, *px;
    cudaGetSymbolAddress(&pq, g_q);  cudaGetSymbolAddress(&pk, g_k);
    cudaGetSymbolAddress(&pv, g_v);  cudaGetSymbolAddress(&pt, g_t);
    cudaGetSymbolAddress(&px, g_x);

    void *srch,*srcl,*wqh,*wql,*wkh,*wkl,*wvh,*wvl,*woh,*wol,*w1h,*w1l,*w2h,*w2l;
    void *xh,*xl,*aoh,*aol,*ffh,*ffl;
    cudaGetSymbolAddress(&srch, s_src_h); cudaGetSymbolAddress(&srcl, s_src_l);
    cudaGetSymbolAddress(&wqh, s_wq_h);   cudaGetSymbolAddress(&wql, s_wq_l);
    cudaGetSymbolAddress(&wkh, s_wk_h);   cudaGetSymbolAddress(&wkl, s_wk_l);
    cudaGetSymbolAddress(&wvh, s_wv_h);   cudaGetSymbolAddress(&wvl, s_wv_l);
    cudaGetSymbolAddress(&woh, s_wo_h);   cudaGetSymbolAddress(&wol, s_wo_l);
    cudaGetSymbolAddress(&w1h, s_w1_h);   cudaGetSymbolAddress(&w1l, s_w1_l);
    cudaGetSymbolAddress(&w2h, s_w2_h);   cudaGetSymbolAddress(&w2l, s_w2_l);
    cudaGetSymbolAddress(&xh,  s_x_h);    cudaGetSymbolAddress(&xl,  s_x_l);
    cudaGetSymbolAddress(&aoh, s_ao_h);   cudaGetSymbolAddress(&aol, s_ao_l);
    cudaGetSymbolAddress(&ffh, s_ff_h);   cudaGetSymbolAddress(&ffl, s_ff_l);

    cudaFuncSetAttribute((const void*)mma_gemm<0, 0>,
                         cudaFuncAttributeMaxDynamicSharedMemorySize, GEMM_SMEM_BYTES);
    cudaFuncSetAttribute((const void*)mma_gemm<0, 1>,
                         cudaFuncAttributeMaxDynamicSharedMemorySize, GEMM_SMEM_BYTES);
    cudaFuncSetAttribute((const void*)mma_gemm<1, 1>,
                         cudaFuncAttributeMaxDynamicSharedMemorySize, GEMM_SMEM_BYTES);

    // split fp32 -> bf16 hi/lo (src + 6 weight matrices)
    {
        const int nSrc4 = M_ * D_ / 4;
        const int nW4   = D_ * D_ / 4;
        const int nW14  = FF_ * D_ / 4;
        split_kernel<<<nSrc4 / 256, 256>>>((const float4*)src, (uint2*)srch, (uint2*)srcl, nSrc4);
        split_kernel<<<nW4 / 256, 256>>>((const float4*)Wq, (uint2*)wqh, (uint2*)wql, nW4);
        split_kernel<<<nW4 / 256, 256>>>((const float4*)Wk, (uint2*)wkh, (uint2*)wkl, nW4);
        split_kernel<<<nW4 / 256, 256>>>((const float4*)Wv, (uint2*)wvh, (uint2*)wvl, nW4);
        split_kernel<<<nW4 / 256, 256>>>((const float4*)Wo, (uint2*)woh, (uint2*)wol, nW4);
        split_kernel<<<nW14 / 256, 256>>>((const float4*)W1, (uint2*)w1h, (uint2*)w1l, nW14);
        split_kernel<<<nW14 / 256, 256>>>((const float4*)W2, (uint2*)w2h, (uint2*)w2l, nW14);
    }

    const dim3 blk(256);
    const dim3 gD(D_ / 128, M_ / 128);    // (8, 32)
    const dim3 gF(FF_ / 128, M_ / 128);   // (32, 32)

    // QKV projections (HMMA, fp32 output)
    mma_gemm<0, 0><<<gD, blk, GEMM_SMEM_BYTES>>>(
        (const __nv_bfloat16*)srch, (const __nv_bfloat16*)srcl,
        (const __nv_bfloat16*)wqh,  (const __nv_bfloat16*)wql,
        nullptr, (float*)pq, nullptr, nullptr, D_, D_);
    mma_gemm<0, 0><<<gD, blk, GEMM_SMEM_BYTES>>>(
        (const __nv_bfloat16*)srch, (const __nv_bfloat16*)srcl,
        (const __nv_bfloat16*)wkh,  (const __nv_bfloat16*)wkl,
        nullptr, (float*)pk, nullptr, nullptr, D_, D_);
    mma_gemm<0, 0><<<gD, blk, GEMM_SMEM_BYTES>>>(
        (const __nv_bfloat16*)srch, (const __nv_bfloat16*)srcl,
        (const __nv_bfloat16*)wvh,  (const __nv_bfloat16*)wvl,
        nullptr, (float*)pv, nullptr, nullptr, D_, D_);

    // attention (fp32 math, bf16 hi/lo output)
    attn_kernel<<<512, 128>>>((const float*)pq, (const float*)pk, (const float*)pv,
                              coords, (__nv_bfloat16*)aoh, (__nv_bfloat16*)aol);

    // output projection -> fp32 t ; residual + LN1 -> x (fp32 + bf16 hi/lo)
    mma_gemm<0, 0><<<gD, blk, GEMM_SMEM_BYTES>>>(
        (const __nv_bfloat16*)aoh, (const __nv_bfloat16*)aol,
        (const __nv_bfloat16*)woh, (const __nv_bfloat16*)wol,
        nullptr, (float*)pt, nullptr, nullptr, D_, D_);
    add_ln_kernel<<<M_, 256>>>(src, (const float*)pt, g1, be1, (float*)px,
                               (__nv_bfloat16*)xh, (__nv_bfloat16*)xl);

    // FFN1 (bias + exact gelu, bf16 hi/lo output)
    mma_gemm<1, 1><<<gF, blk, GEMM_SMEM_BYTES>>>(
        (const __nv_bfloat16*)xh,  (const __nv_bfloat16*)xl,
        (const __nv_bfloat16*)w1h, (const __nv_bfloat16*)w1l,
        b1, nullptr, (__nv_bfloat16*)ffh, (__nv_bfloat16*)ffl, FF_, D_);

    // FFN2 (bias, fp32 output) ; residual + LN2 -> out
    mma_gemm<0, 0><<<gD, blk, GEMM_SMEM_BYTES>>>(
        (const __nv_bfloat16*)ffh, (const __nv_bfloat16*)ffl,
        (const __nv_bfloat16*)w2h, (const __nv_bfloat16*)w2l,
        b2, (float*)pt, nullptr, nullptr, D_, FF_);
    add_ln_kernel<<<M_, 256>>>((const float*)px, (const float*)pt, g2, be2, out,
                               nullptr, nullptr);
}

// round 4
// speedup vs baseline: 3.7676x; 1.8414x over previous
#include <cuda_runtime.h>
#include <cuda_bf16.h>
#include <math.h>
#include <stdint.h>

#define B_   4
#define N_   1024
#define D_   1024
#define H_   16
#define HD_  64
#define FF_  4096
#define M_   (B_ * N_)   // 4096 rows

// ---------------- scratch (static device globals; no allocs allowed) ----------------
__device__ float g_t [M_ * D_];   // src2 / ffn2 output temp (fp32)
__device__ float g_x [M_ * D_];   // post-LN1 activations (fp32)

// bf16 hi/lo split buffers
__device__ __nv_bfloat16 s_src_h[M_ * D_],  s_src_l[M_ * D_];
__device__ __nv_bfloat16 s_wq_h [D_ * D_],  s_wq_l [D_ * D_];
__device__ __nv_bfloat16 s_wk_h [D_ * D_],  s_wk_l [D_ * D_];
__device__ __nv_bfloat16 s_wv_h [D_ * D_],  s_wv_l [D_ * D_];
__device__ __nv_bfloat16 s_wo_h [D_ * D_],  s_wo_l [D_ * D_];
__device__ __nv_bfloat16 s_w1_h [FF_ * D_], s_w1_l [FF_ * D_];
__device__ __nv_bfloat16 s_w2_h [D_ * FF_], s_w2_l [D_ * FF_];
__device__ __nv_bfloat16 s_x_h  [M_ * D_],  s_x_l  [M_ * D_];
__device__ __nv_bfloat16 s_ao_h [M_ * D_],  s_ao_l [M_ * D_];
__device__ __nv_bfloat16 s_ff_h [M_ * FF_], s_ff_l [M_ * FF_];
__device__ __nv_bfloat16 s_q_h  [M_ * D_],  s_q_l  [M_ * D_];
__device__ __nv_bfloat16 s_k_h  [M_ * D_],  s_k_l  [M_ * D_];
__device__ __nv_bfloat16 s_v_h  [M_ * D_],  s_v_l  [M_ * D_];

// ---------------- PTX helpers (Ampere-era only: valid at compute_103 base) ----------
__device__ __forceinline__ uint32_t s2u(const void* p) {
    uint32_t a;
    asm("{ .reg .u64 t; cvta.to.shared.u64 t, %1; cvt.u32.u64 %0, t; }" : "=r"(a) : "l"(p));
    return a;
}
__device__ __forceinline__ void cp_async16(uint32_t saddr, const void* g) {
    asm volatile("cp.async.cg.shared.global [%0], [%1], 16;" :: "r"(saddr), "l"(g) : "memory");
}
#define CP_COMMIT()  asm volatile("cp.async.commit_group;" ::: "memory")
#define CP_WAIT(n)   asm volatile("cp.async.wait_group %0;" :: "n"(n) : "memory")

__device__ __forceinline__ void ldsm4(uint32_t* r, uint32_t addr) {
    asm volatile("ldmatrix.sync.aligned.m8n8.x4.shared.b16 {%0,%1,%2,%3}, [%4];"
                 : "=r"(r[0]), "=r"(r[1]), "=r"(r[2]), "=r"(r[3]) : "r"(addr));
}
__device__ __forceinline__ void ldsm4t(uint32_t* r, uint32_t addr) {
    asm volatile("ldmatrix.sync.aligned.m8n8.x4.trans.shared.b16 {%0,%1,%2,%3}, [%4];"
                 : "=r"(r[0]), "=r"(r[1]), "=r"(r[2]), "=r"(r[3]) : "r"(addr));
}
__device__ __forceinline__ void mma16816(float* c, const uint32_t* a, const uint32_t* b) {
    asm volatile(
        "mma.sync.aligned.m16n8k16.row.col.f32.bf16.bf16.f32 "
        "{%0,%1,%2,%3}, {%4,%5,%6,%7}, {%8,%9}, {%0,%1,%2,%3};"
        : "+f"(c[0]), "+f"(c[1]), "+f"(c[2]), "+f"(c[3])
        : "r"(a[0]), "r"(a[1]), "r"(a[2]), "r"(a[3]), "r"(b[0]), "r"(b[1]));
}

#define SWZ(o) ((o) ^ (((o) >> 3) & 0x70))

__device__ __forceinline__ void pack_hl(float a, float b, uint32_t& hi, uint32_t& lo) {
    __nv_bfloat16 ha = __float2bfloat16(a), hb = __float2bfloat16(b);
    __nv_bfloat162 hp = __halves2bfloat162(ha, hb);
    hi = *(uint32_t*)&hp;
    __nv_bfloat162 lp = __halves2bfloat162(
        __float2bfloat16(a - __bfloat162float(ha)),
        __float2bfloat16(b - __bfloat162float(hb)));
    lo = *(uint32_t*)&lp;
}

// ---------------- split fp32 -> bf16 (hi, lo) ----------------
__global__ __launch_bounds__(256)
void split_kernel(const float4* __restrict__ x, uint2* __restrict__ hi,
                  uint2* __restrict__ lo, int n4) {
    int i = blockIdx.x * 256 + threadIdx.x;
    if (i >= n4) return;
    float4 v = x[i];
    uint32_t h0, l0, h1, l1;
    pack_hl(v.x, v.y, h0, l0);
    pack_hl(v.z, v.w, h1, l1);
    hi[i] = make_uint2(h0, h1);
    lo[i] = make_uint2(l0, l1);
}

// ---------------- HMMA GEMM: C[M,Nn] = A[M,K] @ W[Nn,K]^T (3-term bf16 split) -------
#define STAGE_BYTES 65536
#define GEMM_SMEM_BYTES (2 * STAGE_BYTES)

template <int ACT, int OUTBF16>
__global__ __launch_bounds__(256, 1)
void mma_gemm(const __nv_bfloat16* __restrict__ Ah, const __nv_bfloat16* __restrict__ Al,
              const __nv_bfloat16* __restrict__ Wh, const __nv_bfloat16* __restrict__ Wl,
              const float* __restrict__ bias,
              float* __restrict__ Cf,
              __nv_bfloat16* __restrict__ Ch, __nv_bfloat16* __restrict__ Cl,
              int Nn, int K) {
    extern __shared__ char dsm[];
    const uint32_t sb = s2u(dsm);

    const int tid  = threadIdx.x;
    const int wid  = tid >> 5;
    const int lane = tid & 31;
    const int wm   = wid & 1;
    const int wn   = wid >> 1;
    const int mBase = blockIdx.y * 128;
    const int nBase = blockIdx.x * 128;
    const int NC = K / 64;

    const __nv_bfloat16* gsrc[4] = {
        Ah + (size_t)mBase * K, Al + (size_t)mBase * K,
        Wh + (size_t)nBase * K, Wl + (size_t)nBase * K };

    const int r0 = tid >> 3;
    const int c0 = tid & 7;

    auto load_stage = [&](int buf, int kcol) {
        const uint32_t stage = sb + buf * STAGE_BYTES;
#pragma unroll
        for (int sub = 0; sub < 4; sub++) {
            const __nv_bfloat16* G = gsrc[sub] + kcol;
            const uint32_t soff = stage + sub * 16384;
#pragma unroll
            for (int j = 0; j < 4; j++) {
                const int r = r0 + 32 * j;
                const uint32_t off = (uint32_t)(r * 128 + c0 * 16);
                cp_async16(soff + SWZ(off), G + (size_t)r * K + c0 * 8);
            }
        }
    };

    float acc[4][4][4];
#pragma unroll
    for (int i = 0; i < 4; i++)
#pragma unroll
        for (int j = 0; j < 4; j++)
#pragma unroll
            for (int t = 0; t < 4; t++) acc[i][j][t] = 0.f;

    const int aRow = wm * 64 + (lane & 15);
    const int aColSel = (lane >> 4) * 8;
    const int bRow = wn * 32 + ((lane >> 4) << 3) + (lane & 7);
    const int bColSel = ((lane >> 3) & 1) * 8;

    load_stage(0, 0);
    CP_COMMIT();

    for (int c = 0; c < NC; c++) {
        if (c + 1 < NC) {
            load_stage((c + 1) & 1, (c + 1) * 64);
            CP_COMMIT();
            CP_WAIT(1);
        } else {
            CP_WAIT(0);
        }
        __syncthreads();

        const uint32_t stage = sb + (c & 1) * STAGE_BYTES;
        const uint32_t sAh = stage, sAl = stage + 16384;
        const uint32_t sWh = stage + 32768, sWl = stage + 49152;

#pragma unroll
        for (int ks = 0; ks < 4; ks++) {
            const int kc = ks * 16;
            uint32_t ah[4][4], al[4][4];
#pragma unroll
            for (int fm = 0; fm < 4; fm++) {
                const uint32_t off = (uint32_t)((aRow + fm * 16) * 128 + (kc + aColSel) * 2);
                ldsm4(ah[fm], sAh + SWZ(off));
                ldsm4(al[fm], sAl + SWZ(off));
            }
            uint32_t bh[4][2], bl[4][2];
#pragma unroll
            for (int nh = 0; nh < 2; nh++) {
                const uint32_t off = (uint32_t)((bRow + nh * 16) * 128 + (kc + bColSel) * 2);
                uint32_t t[4];
                ldsm4(t, sWh + SWZ(off));
                bh[nh*2][0] = t[0]; bh[nh*2][1] = t[1];
                bh[nh*2+1][0] = t[2]; bh[nh*2+1][1] = t[3];
                ldsm4(t, sWl + SWZ(off));
                bl[nh*2][0] = t[0]; bl[nh*2][1] = t[1];
                bl[nh*2+1][0] = t[2]; bl[nh*2+1][1] = t[3];
            }
#pragma unroll
            for (int fm = 0; fm < 4; fm++)
#pragma unroll
                for (int fn = 0; fn < 4; fn++) {
                    mma16816(acc[fm][fn], ah[fm], bh[fn]);
                    mma16816(acc[fm][fn], ah[fm], bl[fn]);
                    mma16816(acc[fm][fn], al[fm], bh[fn]);
                }
        }
        __syncthreads();
    }

    const int erow = mBase + wm * 64 + (lane >> 2);
    const int ecol = nBase + wn * 32 + (lane & 3) * 2;
#pragma unroll
    for (int fm = 0; fm < 4; fm++) {
#pragma unroll
        for (int fn = 0; fn < 4; fn++) {
            const int col = ecol + fn * 8;
#pragma unroll
            for (int half = 0; half < 2; half++) {
                const int row = erow + fm * 16 + half * 8;
                float v0 = acc[fm][fn][half * 2 + 0];
                float v1 = acc[fm][fn][half * 2 + 1];
                if (bias) { v0 += bias[col]; v1 += bias[col + 1]; }
                if (ACT == 1) {
                    v0 = 0.5f * v0 * (1.f + erff(v0 * 0.70710678118654752f));
                    v1 = 0.5f * v1 * (1.f + erff(v1 * 0.70710678118654752f));
                }
                const size_t base = (size_t)row * Nn + col;
                if (OUTBF16) {
                    uint32_t hp, lp;
                    pack_hl(v0, v1, hp, lp);
                    *(uint32_t*)(Ch + base) = hp;
                    *(uint32_t*)(Cl + base) = lp;
                } else {
                    *(float2*)(Cf + base) = make_float2(v0, v1);
                }
            }
        }
    }
}

// ---------------- flash attention with mma.sync (3-term bf16 splits) ----------------
// CTA = (b, h, 128-query tile). 8 warps x 16 rows. KV tiles of 64 keys, double-buf.
// smem: Qh[0,16K) Ql[16K,32K) stages at 32768 + s*33792:
//       Kh +0, Kl +8192, Vh +16384, Vl +24576, coords(int2 x64) +32768
#define ATT_STAGE 33792
#define ATT_SMEM  (32768 + 2 * ATT_STAGE)

__global__ __launch_bounds__(256, 1)
void attn_mma_kernel(const __nv_bfloat16* __restrict__ qh, const __nv_bfloat16* __restrict__ ql,
                     const __nv_bfloat16* __restrict__ kh, const __nv_bfloat16* __restrict__ kl,
                     const __nv_bfloat16* __restrict__ vh, const __nv_bfloat16* __restrict__ vl,
                     const int* __restrict__ coords,
                     __nv_bfloat16* __restrict__ aoh, __nv_bfloat16* __restrict__ aol) {
    extern __shared__ char dsm[];
    const uint32_t sb = s2u(dsm);

    const int tid  = threadIdx.x;
    const int wid  = tid >> 5;
    const int lane = tid & 31;
    const int qt = blockIdx.x & 7;
    const int h  = (blockIdx.x >> 3) & 15;
    const int b  = blockIdx.x >> 7;
    const int qbase = qt * 128;

    const float slope = exp2f(-0.5f * (float)(h + 1));
    const float scale = 0.125f;

    // this thread's two query rows (m16n8 frag layout: rows lane/4 and lane/4+8)
    const int r0 = wid * 16 + (lane >> 2);
    const int grow0 = b * N_ + qbase + r0;
    const float xi0 = (float)coords[grow0 * 2 + 0];
    const float yi0 = (float)coords[grow0 * 2 + 1];
    const float xi1 = (float)coords[(grow0 + 8) * 2 + 0];
    const float yi1 = (float)coords[(grow0 + 8) * 2 + 1];

    // ---- load Q hi/lo (128 x 64 bf16 each) ----
    {
        const int rr = tid >> 3, cc = tid & 7;
#pragma unroll
        for (int j = 0; j < 4; j++) {
            const int r = rr + 32 * j;
            const size_t go = (size_t)(b * N_ + qbase + r) * D_ + h * HD_ + cc * 8;
            const uint32_t off = SWZ((uint32_t)(r * 128 + cc * 16));
            cp_async16(sb + off, qh + go);
            cp_async16(sb + 16384 + off, ql + go);
        }
    }
    CP_COMMIT();

    auto load_kv = [&](int t, int buf) {
        const uint32_t st = sb + 32768 + buf * ATT_STAGE;
        const int kt = t * 64;
        const int rr = tid >> 2, cc = tid & 3;
        const size_t gbase = (size_t)(b * N_ + kt) * D_ + h * HD_;
        const __nv_bfloat16* G[4] = { kh + gbase, kl + gbase, vh + gbase, vl + gbase };
#pragma unroll
        for (int m = 0; m < 4; m++) {
#pragma unroll
            for (int j = 0; j < 2; j++) {
                const int ch = cc + 4 * j;
                cp_async16(st + m * 8192 + SWZ((uint32_t)(rr * 128 + ch * 16)),
                           G[m] + (size_t)rr * D_ + ch * 8);
            }
        }
        if (tid < 32)
            cp_async16(st + 32768 + tid * 16,
                       (const char*)coords + (size_t)(b * N_ + kt) * 8 + tid * 16);
    };

    load_kv(0, 0);
    CP_COMMIT();

    float m0 = -1e30f, m1 = -1e30f, l0 = 0.f, l1 = 0.f;
    float acc_o[8][4];
#pragma unroll
    for (int f = 0; f < 8; f++)
#pragma unroll
        for (int t = 0; t < 4; t++) acc_o[f][t] = 0.f;

    const int aRow  = wid * 16 + (lane & 15);
    const int aCol  = (lane >> 4) * 8;
    const int bRowK = ((lane >> 4) << 3) + (lane & 7);
    const int bColK = ((lane >> 3) & 1) * 8;
    const int vRow  = ((lane >> 3) & 1) * 8 + (lane & 7);
    const int vCol  = (lane >> 4) * 8;

    for (int t = 0; t < 16; t++) {
        const int buf = t & 1;
        if (t + 1 < 16) { load_kv(t + 1, 1 - buf); CP_COMMIT(); CP_WAIT(1); }
        else            { CP_WAIT(0); }
        __syncthreads();

        const uint32_t st = sb + 32768 + buf * ATT_STAGE;
        const uint32_t sKh = st, sKl = st + 8192, sVh = st + 16384, sVl = st + 24576;
        const int2* kco = (const int2*)(dsm + 32768 + buf * ATT_STAGE + 32768);

        // ---- S = Q K^T (3-term) ----
        float accs[8][4];
#pragma unroll
        for (int f = 0; f < 8; f++)
#pragma unroll
            for (int u = 0; u < 4; u++) accs[f][u] = 0.f;

#pragma unroll
        for (int ks = 0; ks < 4; ks++) {
            const int kc = ks * 16;
            uint32_t ah[4], al[4];
            const uint32_t aoff = SWZ((uint32_t)(aRow * 128 + (kc + aCol) * 2));
            ldsm4(ah, sb + aoff);
            ldsm4(al, sb + 16384 + aoff);
#pragma unroll
            for (int nh = 0; nh < 4; nh++) {
                const uint32_t boff = SWZ((uint32_t)((nh * 16 + bRowK) * 128 + (kc + bColK) * 2));
                uint32_t tb[4], tl[4];
                ldsm4(tb, sKh + boff);
                ldsm4(tl, sKl + boff);
                uint32_t bh0[2] = { tb[0], tb[1] }, bh1[2] = { tb[2], tb[3] };
                uint32_t bl0[2] = { tl[0], tl[1] }, bl1[2] = { tl[2], tl[3] };
                mma16816(accs[nh*2],   ah, bh0);
                mma16816(accs[nh*2],   ah, bl0);
                mma16816(accs[nh*2],   al, bh0);
                mma16816(accs[nh*2+1], ah, bh1);
                mma16816(accs[nh*2+1], ah, bl1);
                mma16816(accs[nh*2+1], al, bh1);
            }
        }

        // ---- scale + ALiBi bias ----
#pragma unroll
        for (int f = 0; f < 8; f++) {
            const int c = f * 8 + (lane & 3) * 2;
            const int2 ca = kco[c], cb = kco[c + 1];
            const float xa = (float)ca.x, ya = (float)ca.y;
            const float xb = (float)cb.x, yb = (float)cb.y;
            accs[f][0] = fmaf(accs[f][0], scale, slope * (fabsf(xi0 - xa) + fabsf(yi0 - ya)));
            accs[f][1] = fmaf(accs[f][1], scale, slope * (fabsf(xi0 - xb) + fabsf(yi0 - yb)));
            accs[f][2] = fmaf(accs[f][2], scale, slope * (fabsf(xi1 - xa) + fabsf(yi1 - ya)));
            accs[f][3] = fmaf(accs[f][3], scale, slope * (fabsf(xi1 - xb) + fabsf(yi1 - yb)));
        }

        // ---- online softmax ----
        float mx0 = -1e30f, mx1 = -1e30f;
#pragma unroll
        for (int f = 0; f < 8; f++) {
            mx0 = fmaxf(mx0, fmaxf(accs[f][0], accs[f][1]));
            mx1 = fmaxf(mx1, fmaxf(accs[f][2], accs[f][3]));
        }
        mx0 = fmaxf(mx0, __shfl_xor_sync(0xffffffffu, mx0, 1));
        mx0 = fmaxf(mx0, __shfl_xor_sync(0xffffffffu, mx0, 2));
        mx1 = fmaxf(mx1, __shfl_xor_sync(0xffffffffu, mx1, 1));
        mx1 = fmaxf(mx1, __shfl_xor_sync(0xffffffffu, mx1, 2));
        const float nm0 = fmaxf(m0, mx0), nm1 = fmaxf(m1, mx1);
        const float cr0 = __expf(m0 - nm0), cr1 = __expf(m1 - nm1);
        m0 = nm0; m1 = nm1;
        l0 *= cr0; l1 *= cr1;
#pragma unroll
        for (int f = 0; f < 8; f++) {
            acc_o[f][0] *= cr0; acc_o[f][1] *= cr0;
            acc_o[f][2] *= cr1; acc_o[f][3] *= cr1;
        }
#pragma unroll
        for (int f = 0; f < 8; f++) {
            accs[f][0] = __expf(accs[f][0] - nm0);
            accs[f][1] = __expf(accs[f][1] - nm0);
            accs[f][2] = __expf(accs[f][2] - nm1);
            accs[f][3] = __expf(accs[f][3] - nm1);
            l0 += accs[f][0] + accs[f][1];
            l1 += accs[f][2] + accs[f][3];
        }

        // ---- O += P V (3-term; P hi/lo from registers, V^T via ldmatrix.trans) ----
#pragma unroll
        for (int kg = 0; kg < 4; kg++) {
            const float* s0 = accs[2 * kg];
            const float* s1 = accs[2 * kg + 1];
            uint32_t pah[4], pal[4];
            pack_hl(s0[0], s0[1], pah[0], pal[0]);
            pack_hl(s0[2], s0[3], pah[1], pal[1]);
            pack_hl(s1[0], s1[1], pah[2], pal[2]);
            pack_hl(s1[2], s1[3], pah[3], pal[3]);
#pragma unroll
            for (int vi = 0; vi < 4; vi++) {
                const uint32_t voff =
                    SWZ((uint32_t)((kg * 16 + vRow) * 128 + (vi * 16 + vCol) * 2));
                uint32_t tv[4], tw[4];
                ldsm4t(tv, sVh + voff);
                ldsm4t(tw, sVl + voff);
                uint32_t bvh0[2] = { tv[0], tv[1] }, bvh1[2] = { tv[2], tv[3] };
                uint32_t bvl0[2] = { tw[0], tw[1] }, bvl1[2] = { tw[2], tw[3] };
                mma16816(acc_o[vi*2],   pah, bvh0);
                mma16816(acc_o[vi*2],   pah, bvl0);
                mma16816(acc_o[vi*2],   pal, bvh0);
                mma16816(acc_o[vi*2+1], pah, bvh1);
                mma16816(acc_o[vi*2+1], pah, bvl1);
                mma16816(acc_o[vi*2+1], pal, bvh1);
            }
        }
        __syncthreads();
    }

    // ---- finalize: normalize, write bf16 hi/lo ----
    l0 += __shfl_xor_sync(0xffffffffu, l0, 1);
    l0 += __shfl_xor_sync(0xffffffffu, l0, 2);
    l1 += __shfl_xor_sync(0xffffffffu, l1, 1);
    l1 += __shfl_xor_sync(0xffffffffu, l1, 2);
    const float inv0 = 1.f / l0, inv1 = 1.f / l1;
#pragma unroll
    for (int f = 0; f < 8; f++) {
        const int c = f * 8 + (lane & 3) * 2;
        const size_t base0 = (size_t)grow0 * D_ + h * HD_ + c;
        const size_t base1 = (size_t)(grow0 + 8) * D_ + h * HD_ + c;
        uint32_t hp, lp;
        pack_hl(acc_o[f][0] * inv0, acc_o[f][1] * inv0, hp, lp);
        *(uint32_t*)(aoh + base0) = hp;
        *(uint32_t*)(aol + base0) = lp;
        pack_hl(acc_o[f][2] * inv1, acc_o[f][3] * inv1, hp, lp);
        *(uint32_t*)(aoh + base1) = hp;
        *(uint32_t*)(aol + base1) = lp;
    }
}

// ---------------- fused residual add + LayerNorm (+ optional bf16 hi/lo emit) -------
__global__ __launch_bounds__(256)
void add_ln_kernel(const float* __restrict__ a, const float* __restrict__ bsum,
                   const float* __restrict__ g, const float* __restrict__ be,
                   float* __restrict__ out,
                   __nv_bfloat16* __restrict__ hi, __nv_bfloat16* __restrict__ lo) {
    const int row = blockIdx.x;
    const int tid = threadIdx.x;
    const float* pa = a    + (size_t)row * D_;
    const float* pb = bsum + (size_t)row * D_;

    float v[4];
    float s = 0.f, ss = 0.f;
#pragma unroll
    for (int i = 0; i < 4; i++) {
        const int c = tid + 256 * i;
        const float t = pa[c] + pb[c];
        v[i] = t; s += t; ss = fmaf(t, t, ss);
    }
#pragma unroll
    for (int o = 16; o > 0; o >>= 1) {
        s  += __shfl_xor_sync(0xffffffffu, s,  o);
        ss += __shfl_xor_sync(0xffffffffu, ss, o);
    }
    __shared__ float rs[8], rss[8];
    __shared__ float smu, sinv;
    const int w = tid >> 5;
    if ((tid & 31) == 0) { rs[w] = s; rss[w] = ss; }
    __syncthreads();
    if (tid == 0) {
        float S = 0.f, SS = 0.f;
#pragma unroll
        for (int i = 0; i < 8; i++) { S += rs[i]; SS += rss[i]; }
        const float mu  = S * (1.f / 1024.f);
        const float var = SS * (1.f / 1024.f) - mu * mu;
        smu = mu; sinv = rsqrtf(var + 1e-5f);
    }
    __syncthreads();
    const float mu = smu, inv = sinv;
#pragma unroll
    for (int i = 0; i < 4; i++) {
        const int c = tid + 256 * i;
        const float o = (v[i] - mu) * inv * g[c] + be[c];
        out[(size_t)row * D_ + c] = o;
        if (hi) {
            const __nv_bfloat16 hh = __float2bfloat16(o);
            hi[(size_t)row * D_ + c] = hh;
            lo[(size_t)row * D_ + c] = __float2bfloat16(o - __bfloat162float(hh));
        }
    }
}

// ---------------- launch ----------------
extern "C" void kernel_launch(void* const* d_in, const int* in_sizes, int n_in,
                              void* d_out, int out_size) {
    const float* src    = (const float*)d_in[0];
    const int*   coords = (const int*)  d_in[1];
    const float* Wq = (const float*)d_in[2];
    const float* Wk = (const float*)d_in[3];
    const float* Wv = (const float*)d_in[4];
    const float* Wo = (const float*)d_in[5];
    const float* W1 = (const float*)d_in[6];
    const float* b1 = (const float*)d_in[7];
    const float* W2 = (const float*)d_in[8];
    const float* b2 = (const float*)d_in[9];
    const float* g1 = (const float*)d_in[10];
    const float* be1= (const float*)d_in[11];
    const float* g2 = (const float*)d_in[12];
    const float* be2= (const float*)d_in[13];
    float* out = (float*)d_out;

    void *pt, *px;
    cudaGetSymbolAddress(&pt, g_t);
    cudaGetSymbolAddress(&px, g_x);

    void *srch,*srcl,*wqh,*wql,*wkh,*wkl,*wvh,*wvl,*woh,*wol,*w1h,*w1l,*w2h,*w2l;
    void *xh,*xl,*aoh,*aol,*ffh,*ffl,*qhh,*qll,*khh,*kll,*vhh,*vll;
    cudaGetSymbolAddress(&srch, s_src_h); cudaGetSymbolAddress(&srcl, s_src_l);
    cudaGetSymbolAddress(&wqh, s_wq_h);   cudaGetSymbolAddress(&wql, s_wq_l);
    cudaGetSymbolAddress(&wkh, s_wk_h);   cudaGetSymbolAddress(&wkl, s_wk_l);
    cudaGetSymbolAddress(&wvh, s_wv_h);   cudaGetSymbolAddress(&wvl, s_wv_l);
    cudaGetSymbolAddress(&woh, s_wo_h);   cudaGetSymbolAddress(&wol, s_wo_l);
    cudaGetSymbolAddress(&w1h, s_w1_h);   cudaGetSymbolAddress(&w1l, s_w1_l);
    cudaGetSymbolAddress(&w2h, s_w2_h);   cudaGetSymbolAddress(&w2l, s_w2_l);
    cudaGetSymbolAddress(&xh,  s_x_h);    cudaGetSymbolAddress(&xl,  s_x_l);
    cudaGetSymbolAddress(&aoh, s_ao_h);   cudaGetSymbolAddress(&aol, s_ao_l);
    cudaGetSymbolAddress(&ffh, s_ff_h);   cudaGetSymbolAddress(&ffl, s_ff_l);
    cudaGetSymbolAddress(&qhh, s_q_h);    cudaGetSymbolAddress(&qll, s_q_l);
    cudaGetSymbolAddress(&khh, s_k_h);    cudaGetSymbolAddress(&kll, s_k_l);
    cudaGetSymbolAddress(&vhh, s_v_h);    cudaGetSymbolAddress(&vll, s_v_l);

    cudaFuncSetAttribute((const void*)mma_gemm<0, 0>,
                         cudaFuncAttributeMaxDynamicSharedMemorySize, GEMM_SMEM_BYTES);
    cudaFuncSetAttribute((const void*)mma_gemm<0, 1>,
                         cudaFuncAttributeMaxDynamicSharedMemorySize, GEMM_SMEM_BYTES);
    cudaFuncSetAttribute((const void*)mma_gemm<1, 1>,
                         cudaFuncAttributeMaxDynamicSharedMemorySize, GEMM_SMEM_BYTES);
    cudaFuncSetAttribute((const void*)attn_mma_kernel,
                         cudaFuncAttributeMaxDynamicSharedMemorySize, ATT_SMEM);

    // split fp32 -> bf16 hi/lo (src + 6 weight matrices)
    {
        const int nSrc4 = M_ * D_ / 4;
        const int nW4   = D_ * D_ / 4;
        const int nW14  = FF_ * D_ / 4;
        split_kernel<<<nSrc4 / 256, 256>>>((const float4*)src, (uint2*)srch, (uint2*)srcl, nSrc4);
        split_kernel<<<nW4 / 256, 256>>>((const float4*)Wq, (uint2*)wqh, (uint2*)wql, nW4);
        split_kernel<<<nW4 / 256, 256>>>((const float4*)Wk, (uint2*)wkh, (uint2*)wkl, nW4);
        split_kernel<<<nW4 / 256, 256>>>((const float4*)Wv, (uint2*)wvh, (uint2*)wvl, nW4);
        split_kernel<<<nW4 / 256, 256>>>((const float4*)Wo, (uint2*)woh, (uint2*)wol, nW4);
        split_kernel<<<nW14 / 256, 256>>>((const float4*)W1, (uint2*)w1h, (uint2*)w1l, nW14);
        split_kernel<<<nW14 / 256, 256>>>((const float4*)W2, (uint2*)w2h, (uint2*)w2l, nW14);
    }

    const dim3 blk(256);
    const dim3 gD(D_ / 128, M_ / 128);    // (8, 32)
    const dim3 gF(FF_ / 128, M_ / 128);   // (32, 32)

    // QKV projections (HMMA, bf16 hi/lo output for the attention kernel)
    mma_gemm<0, 1><<<gD, blk, GEMM_SMEM_BYTES>>>(
        (const __nv_bfloat16*)srch, (const __nv_bfloat16*)srcl,
        (const __nv_bfloat16*)wqh,  (const __nv_bfloat16*)wql,
        nullptr, nullptr, (__nv_bfloat16*)qhh, (__nv_bfloat16*)qll, D_, D_);
    mma_gemm<0, 1><<<gD, blk, GEMM_SMEM_BYTES>>>(
        (const __nv_bfloat16*)srch, (const __nv_bfloat16*)srcl,
        (const __nv_bfloat16*)wkh,  (const __nv_bfloat16*)wkl,
        nullptr, nullptr, (__nv_bfloat16*)khh, (__nv_bfloat16*)kll, D_, D_);
    mma_gemm<0, 1><<<gD, blk, GEMM_SMEM_BYTES>>>(
        (const __nv_bfloat16*)srch, (const __nv_bfloat16*)srcl,
        (const __nv_bfloat16*)wvh,  (const __nv_bfloat16*)wvl,
        nullptr, nullptr, (__nv_bfloat16*)vhh, (__nv_bfloat16*)vll, D_, D_);

    // flash attention (tensor cores, bf16 hi/lo in and out)
    attn_mma_kernel<<<512, 256, ATT_SMEM>>>(
        (const __nv_bfloat16*)qhh, (const __nv_bfloat16*)qll,
        (const __nv_bfloat16*)khh, (const __nv_bfloat16*)kll,
        (const __nv_bfloat16*)vhh, (const __nv_bfloat16*)vll,
        coords, (__nv_bfloat16*)aoh, (__nv_bfloat16*)aol);

    // output projection -> fp32 t ; residual + LN1 -> x (fp32 + bf16 hi/lo)
    mma_gemm<0, 0><<<gD, blk, GEMM_SMEM_BYTES>>>(
        (const __nv_bfloat16*)aoh, (const __nv_bfloat16*)aol,
        (const __nv_bfloat16*)woh, (const __nv_bfloat16*)wol,
        nullptr, (float*)pt, nullptr, nullptr, D_, D_);
    add_ln_kernel<<<M_, 256>>>(src, (const float*)pt, g1, be1, (float*)px,
                               (__nv_bfloat16*)xh, (__nv_bfloat16*)xl);

    // FFN1 (bias + exact gelu, bf16 hi/lo output)
    mma_gemm<1, 1><<<gF, blk, GEMM_SMEM_BYTES>>>(
        (const __nv_bfloat16*)xh,  (const __nv_bfloat16*)xl,
        (const __nv_bfloat16*)w1h, (const __nv_bfloat16*)w1l,
        b1, nullptr, (__nv_bfloat16*)ffh, (__nv_bfloat16*)ffl, FF_, D_);

    // FFN2 (bias, fp32 output) ; residual + LN2 -> out
    mma_gemm<0, 0><<<gD, blk, GEMM_SMEM_BYTES>>>(
        (const __nv_bfloat16*)ffh, (const __nv_bfloat16*)ffl,
        (const __nv_bfloat16*)w2h, (const __nv_bfloat16*)w2l,
        b2, (float*)pt, nullptr, nullptr, D_, FF_);
    add_ln_kernel<<<M_, 256>>>((const float*)px, (const float*)pt, g2, be2, out,
                               nullptr, nullptr);
}